// round 11
// baseline (speedup 1.0000x reference)
#include <cuda_runtime.h>
#include <math.h>

// R10 (60.1us) with k2a+k2b merged into ONE kernel (k_reduce_fused).
//   k1: split-K matvec, SPLITS=512 (unchanged, ~33.7us @ 80% DRAM)
//   k2: fused reduction 512->1 + input + tanh -> yout. 32 CTAs x 1024 thr.
//   k3: flat hebb update, 16384 CTAs, 1 float4/thread (unchanged, 19.0us)

#define N 4096
#define SPLITS 512             // row splits (split-K)
#define ROWS_PER (N / SPLITS)  // 8 rows per split
#define MV_THREADS 256
#define COL_BLOCKS (N / (MV_THREADS * 4))  // 4

// Deterministic split-K scratch (8 MB). No atomics -> bit-identical replays.
__device__ float g_partial[SPLITS * N];

// ---------------------------------------------------------------------------
// Kernel 1: partial matvec, 2048 CTAs, 8 fully-unrolled rows. (unchanged)
// ---------------------------------------------------------------------------
__global__ void __launch_bounds__(MV_THREADS) k_matvec_partial(
    const float* __restrict__ yin,
    const float* __restrict__ w,
    const float* __restrict__ alpha,
    const float* __restrict__ hebb)
{
    const int j  = blockIdx.x * (MV_THREADS * 4) + threadIdx.x * 4;
    const int r0 = blockIdx.y * ROWS_PER;

    const float4* __restrict__ wp = reinterpret_cast<const float4*>(w     + (size_t)r0 * N + j);
    const float4* __restrict__ ap = reinterpret_cast<const float4*>(alpha + (size_t)r0 * N + j);
    const float4* __restrict__ hp = reinterpret_cast<const float4*>(hebb  + (size_t)r0 * N + j);
    const int stride4 = N / 4;

    float4 acc = make_float4(0.f, 0.f, 0.f, 0.f);

    #pragma unroll
    for (int i = 0; i < ROWS_PER; ++i) {
        const float  y  = __ldg(&yin[r0 + i]);
        const float4 w4 = __ldcs(wp + (size_t)i * stride4);
        const float4 a4 = __ldcs(ap + (size_t)i * stride4);
        const float4 h4 = __ldg (hp + (size_t)i * stride4);
        acc.x = fmaf(y, fmaf(a4.x, h4.x, w4.x), acc.x);
        acc.y = fmaf(y, fmaf(a4.y, h4.y, w4.y), acc.y);
        acc.z = fmaf(y, fmaf(a4.z, h4.z, w4.z), acc.z);
        acc.w = fmaf(y, fmaf(a4.w, h4.w, w4.w), acc.w);
    }

    *reinterpret_cast<float4*>(&g_partial[(size_t)blockIdx.y * N + j]) = acc;
}

// ---------------------------------------------------------------------------
// Kernel 2 (fused): 512-way column reduction + input + tanh -> yout.
// Grid: 32 CTAs x 1024 threads. CTA owns 128 columns.
// Thread (sg, col): sg = tid>>7 (0..7 split-groups), col = tid&127.
// Each thread sums 64 partials; consecutive threads hit consecutive columns
// (512B coalesced, L2-resident after k1). Then smem reduce 8 -> 1 + tanh.
// ---------------------------------------------------------------------------
#define R_THREADS 1024
#define R_GROUPS  8
#define R_COLS    128                    // columns per CTA
#define R_PER_T   (SPLITS / R_GROUPS)    // 64 partials per thread

__global__ void __launch_bounds__(R_THREADS) k_reduce_fused(
    const float* __restrict__ input,
    float* __restrict__ out_yout)
{
    __shared__ float red[R_GROUPS][R_COLS];

    const int tid = threadIdx.x;
    const int col = tid & (R_COLS - 1);          // 0..127
    const int sg  = tid >> 7;                    // 0..7
    const int j   = blockIdx.x * R_COLS + col;   // global column

    const float* __restrict__ gp = g_partial + (size_t)sg * R_PER_T * N + j;

    float s = 0.f;
    #pragma unroll 16
    for (int p = 0; p < R_PER_T; ++p)
        s += gp[(size_t)p * N];

    red[sg][col] = s;
    __syncthreads();

    if (sg == 0) {
        float t = red[0][col];
        #pragma unroll
        for (int g = 1; g < R_GROUPS; ++g)
            t += red[g][col];
        out_yout[j] = tanhf(t + __ldg(&input[j]));
    }
}

// ---------------------------------------------------------------------------
// Kernel 3: flat hebb update (unchanged — measured 19.0us).
// ---------------------------------------------------------------------------
__global__ void __launch_bounds__(256) k_hebb_update(
    const float* __restrict__ hebb,
    const float* __restrict__ yin,
    const float* __restrict__ yout,   // = d_out
    const float* __restrict__ eta,
    float* __restrict__ out_hebb)     // = d_out + N
{
    const size_t t   = (size_t)blockIdx.x * blockDim.x + threadIdx.x;
    const size_t idx = t * 4;                 // element index in N*N
    const int i = (int)(idx >> 12);           // row (N = 2^12)
    const int j = (int)(idx & (N - 1));       // col

    const float e   = eta[0];
    const float ome = 1.f - e;
    const float yie = yin[i] * e;             // warp-uniform broadcast

    const float4 h  = __ldg(reinterpret_cast<const float4*>(hebb + idx));
    const float4 yo = __ldg(reinterpret_cast<const float4*>(yout + j));

    float4 r;
    r.x = fmaf(ome, h.x, yie * yo.x);
    r.y = fmaf(ome, h.y, yie * yo.y);
    r.z = fmaf(ome, h.z, yie * yo.z);
    r.w = fmaf(ome, h.w, yie * yo.w);

    __stcs(reinterpret_cast<float4*>(out_hebb + idx), r);
}

extern "C" void kernel_launch(void* const* d_in, const int* in_sizes, int n_in,
                              void* d_out, int out_size)
{
    const float* input = (const float*)d_in[0];
    const float* yin   = (const float*)d_in[1];
    const float* hebb  = (const float*)d_in[2];
    const float* w     = (const float*)d_in[3];
    const float* alpha = (const float*)d_in[4];
    const float* eta   = (const float*)d_in[5];

    float* out      = (float*)d_out;
    float* out_yout = out;
    float* out_hebb = out + N;

    dim3 g1(COL_BLOCKS, SPLITS);   // 4 x 512 = 2048 CTAs
    k_matvec_partial<<<g1, MV_THREADS>>>(yin, w, alpha, hebb);

    k_reduce_fused<<<N / R_COLS, R_THREADS>>>(input, out_yout);   // 32 CTAs

    const int hb_blocks = (N * N) / (4 * 256);   // 16384
    k_hebb_update<<<hb_blocks, 256>>>(hebb, yin, out_yout, eta, out_hebb);
}

// round 12
// speedup vs baseline: 1.0048x; 1.0048x over previous
#include <cuda_runtime.h>
#include <math.h>

// R10 (60.1us) with k2a+k2b merged into ONE kernel (k_reduce_fused).
//   k1: split-K matvec, SPLITS=512 (unchanged, ~33.7us @ 80% DRAM)
//   k2: fused reduction 512->1 + input + tanh -> yout. 32 CTAs x 1024 thr.
//   k3: flat hebb update, 16384 CTAs, 1 float4/thread (unchanged, 19.0us)

#define N 4096
#define SPLITS 512             // row splits (split-K)
#define ROWS_PER (N / SPLITS)  // 8 rows per split
#define MV_THREADS 256
#define COL_BLOCKS (N / (MV_THREADS * 4))  // 4

// Deterministic split-K scratch (8 MB). No atomics -> bit-identical replays.
__device__ float g_partial[SPLITS * N];

// ---------------------------------------------------------------------------
// Kernel 1: partial matvec, 2048 CTAs, 8 fully-unrolled rows. (unchanged)
// ---------------------------------------------------------------------------
__global__ void __launch_bounds__(MV_THREADS) k_matvec_partial(
    const float* __restrict__ yin,
    const float* __restrict__ w,
    const float* __restrict__ alpha,
    const float* __restrict__ hebb)
{
    const int j  = blockIdx.x * (MV_THREADS * 4) + threadIdx.x * 4;
    const int r0 = blockIdx.y * ROWS_PER;

    const float4* __restrict__ wp = reinterpret_cast<const float4*>(w     + (size_t)r0 * N + j);
    const float4* __restrict__ ap = reinterpret_cast<const float4*>(alpha + (size_t)r0 * N + j);
    const float4* __restrict__ hp = reinterpret_cast<const float4*>(hebb  + (size_t)r0 * N + j);
    const int stride4 = N / 4;

    float4 acc = make_float4(0.f, 0.f, 0.f, 0.f);

    #pragma unroll
    for (int i = 0; i < ROWS_PER; ++i) {
        const float  y  = __ldg(&yin[r0 + i]);
        const float4 w4 = __ldcs(wp + (size_t)i * stride4);
        const float4 a4 = __ldcs(ap + (size_t)i * stride4);
        const float4 h4 = __ldg (hp + (size_t)i * stride4);
        acc.x = fmaf(y, fmaf(a4.x, h4.x, w4.x), acc.x);
        acc.y = fmaf(y, fmaf(a4.y, h4.y, w4.y), acc.y);
        acc.z = fmaf(y, fmaf(a4.z, h4.z, w4.z), acc.z);
        acc.w = fmaf(y, fmaf(a4.w, h4.w, w4.w), acc.w);
    }

    *reinterpret_cast<float4*>(&g_partial[(size_t)blockIdx.y * N + j]) = acc;
}

// ---------------------------------------------------------------------------
// Kernel 2 (fused): 512-way column reduction + input + tanh -> yout.
// Grid: 32 CTAs x 1024 threads. CTA owns 128 columns.
// Thread (sg, col): sg = tid>>7 (0..7 split-groups), col = tid&127.
// Each thread sums 64 partials; consecutive threads hit consecutive columns
// (512B coalesced, L2-resident after k1). Then smem reduce 8 -> 1 + tanh.
// ---------------------------------------------------------------------------
#define R_THREADS 1024
#define R_GROUPS  8
#define R_COLS    128                    // columns per CTA
#define R_PER_T   (SPLITS / R_GROUPS)    // 64 partials per thread

__global__ void __launch_bounds__(R_THREADS) k_reduce_fused(
    const float* __restrict__ input,
    float* __restrict__ out_yout)
{
    __shared__ float red[R_GROUPS][R_COLS];

    const int tid = threadIdx.x;
    const int col = tid & (R_COLS - 1);          // 0..127
    const int sg  = tid >> 7;                    // 0..7
    const int j   = blockIdx.x * R_COLS + col;   // global column

    const float* __restrict__ gp = g_partial + (size_t)sg * R_PER_T * N + j;

    float s = 0.f;
    #pragma unroll 16
    for (int p = 0; p < R_PER_T; ++p)
        s += gp[(size_t)p * N];

    red[sg][col] = s;
    __syncthreads();

    if (sg == 0) {
        float t = red[0][col];
        #pragma unroll
        for (int g = 1; g < R_GROUPS; ++g)
            t += red[g][col];
        out_yout[j] = tanhf(t + __ldg(&input[j]));
    }
}

// ---------------------------------------------------------------------------
// Kernel 3: flat hebb update (unchanged — measured 19.0us).
// ---------------------------------------------------------------------------
__global__ void __launch_bounds__(256) k_hebb_update(
    const float* __restrict__ hebb,
    const float* __restrict__ yin,
    const float* __restrict__ yout,   // = d_out
    const float* __restrict__ eta,
    float* __restrict__ out_hebb)     // = d_out + N
{
    const size_t t   = (size_t)blockIdx.x * blockDim.x + threadIdx.x;
    const size_t idx = t * 4;                 // element index in N*N
    const int i = (int)(idx >> 12);           // row (N = 2^12)
    const int j = (int)(idx & (N - 1));       // col

    const float e   = eta[0];
    const float ome = 1.f - e;
    const float yie = yin[i] * e;             // warp-uniform broadcast

    const float4 h  = __ldg(reinterpret_cast<const float4*>(hebb + idx));
    const float4 yo = __ldg(reinterpret_cast<const float4*>(yout + j));

    float4 r;
    r.x = fmaf(ome, h.x, yie * yo.x);
    r.y = fmaf(ome, h.y, yie * yo.y);
    r.z = fmaf(ome, h.z, yie * yo.z);
    r.w = fmaf(ome, h.w, yie * yo.w);

    __stcs(reinterpret_cast<float4*>(out_hebb + idx), r);
}

extern "C" void kernel_launch(void* const* d_in, const int* in_sizes, int n_in,
                              void* d_out, int out_size)
{
    const float* input = (const float*)d_in[0];
    const float* yin   = (const float*)d_in[1];
    const float* hebb  = (const float*)d_in[2];
    const float* w     = (const float*)d_in[3];
    const float* alpha = (const float*)d_in[4];
    const float* eta   = (const float*)d_in[5];

    float* out      = (float*)d_out;
    float* out_yout = out;
    float* out_hebb = out + N;

    dim3 g1(COL_BLOCKS, SPLITS);   // 4 x 512 = 2048 CTAs
    k_matvec_partial<<<g1, MV_THREADS>>>(yin, w, alpha, hebb);

    k_reduce_fused<<<N / R_COLS, R_THREADS>>>(input, out_yout);   // 32 CTAs

    const int hb_blocks = (N * N) / (4 * 256);   // 16384
    k_hebb_update<<<hb_blocks, 256>>>(hebb, yin, out_yout, eta, out_hebb);
}